// round 1
// baseline (speedup 1.0000x reference)
#include <cuda_runtime.h>
#include <math.h>

#define B_ 256
#define H_ 1024
#define P_ 3
#define S_ 512
#define EPSBN 1e-5f

// ---------------- scratch (static device arrays; no cudaMalloc) ----------------
__device__ float g_gi[B_ * 3 * H_];
__device__ float g_gh[B_ * 3 * H_];
__device__ float g_h[B_ * H_];
__device__ float g_q[B_ * H_];
__device__ float g_ctx[B_ * H_];
__device__ float g_y[B_ * H_];
__device__ float g_mu[H_];
__device__ float g_rstd[H_];

// =====================================================================
// GEMM: C[M,N] = act( [A1|A2][M,K1+K2] @ W[N,K]^T + bias[N] )
// =====================================================================
#define BM 64
#define BN 64
#define BK 16

__global__ void gemm_kernel(const float* __restrict__ A1, int K1,
                            const float* __restrict__ A2, int K2,
                            const float* __restrict__ W,
                            const float* __restrict__ bias,
                            float* __restrict__ C,
                            int M, int N, int do_relu)
{
    const int K = K1 + K2;
    __shared__ __align__(16) float As[BK][BM];
    __shared__ __align__(16) float Bs[BK][BN];

    const int bm = blockIdx.y * BM;
    const int bn = blockIdx.x * BN;
    const int tid = threadIdx.x;
    const int tx = tid & 15;
    const int ty = tid >> 4;
    const int lrow = tid >> 2;          // 0..63
    const int lcol = (tid & 3) << 2;    // 0,4,8,12

    float acc[4][4] = {};

    const float* A1row = A1 + (size_t)(bm + lrow) * (size_t)K1;
    const float* A2row = A2 ? (A2 + (size_t)(bm + lrow) * (size_t)K2) : (const float*)0;
    const float* Wrow  = W + (size_t)(bn + lrow) * (size_t)K;

    for (int k0 = 0; k0 < K; k0 += BK) {
#pragma unroll
        for (int i = 0; i < 4; i++) {
            int k = k0 + lcol + i;
            float v = 0.f;
            if (k < K) v = (k < K1) ? A1row[k] : A2row[k - K1];
            As[lcol + i][lrow] = v;
        }
#pragma unroll
        for (int i = 0; i < 4; i++) {
            int k = k0 + lcol + i;
            Bs[lcol + i][lrow] = (k < K) ? Wrow[k] : 0.f;
        }
        __syncthreads();
#pragma unroll
        for (int kk = 0; kk < BK; kk++) {
            float a[4], b[4];
            *(float4*)a = *(const float4*)&As[kk][ty << 2];
            *(float4*)b = *(const float4*)&Bs[kk][tx << 2];
#pragma unroll
            for (int i = 0; i < 4; i++)
#pragma unroll
                for (int j = 0; j < 4; j++)
                    acc[i][j] += a[i] * b[j];
        }
        __syncthreads();
    }

#pragma unroll
    for (int i = 0; i < 4; i++) {
        int m = bm + (ty << 2) + i;
        if (m >= M) continue;
#pragma unroll
        for (int j = 0; j < 4; j++) {
            int n = bn + (tx << 2) + j;
            if (n >= N) continue;
            float v = acc[i][j] + bias[n];
            if (do_relu) v = fmaxf(v, 0.f);
            C[(size_t)m * N + n] = v;
        }
    }
}

// =====================================================================
// GRU gates
// =====================================================================
__global__ void gru_gate_kernel(const float* __restrict__ h0,
                                float* __restrict__ out_h)
{
    int idx = blockIdx.x * blockDim.x + threadIdx.x;
    int b = idx >> 10;
    int j = idx & (H_ - 1);
    size_t base = (size_t)b * (3 * H_);
    float gir = g_gi[base + j];
    float giz = g_gi[base + H_ + j];
    float gin = g_gi[base + 2 * H_ + j];
    float ghr = g_gh[base + j];
    float ghz = g_gh[base + H_ + j];
    float ghn = g_gh[base + 2 * H_ + j];
    float r = 1.f / (1.f + __expf(-(gir + ghr)));
    float z = 1.f / (1.f + __expf(-(giz + ghz)));
    float n = tanhf(gin + r * ghn);
    float h = (1.f - z) * n + z * h0[idx];
    g_h[idx] = h;
    if (out_h) out_h[idx] = h;
}

// =====================================================================
// Single-pass online-softmax attention, one block per batch row.
// =====================================================================
__global__ void attn_kernel(const float* __restrict__ enc,
                            const int* __restrict__ lens,
                            float* __restrict__ out_ctx,
                            float* __restrict__ out_w)
{
    const int b = blockIdx.x;
    const int tid = threadIdx.x;
    const int warp = tid >> 5, lane = tid & 31;

    __shared__ __align__(16) float q_s[H_];
    __shared__ __align__(16) float tile[8][H_];
    __shared__ float e_chunk[8];
    __shared__ float e_all[S_];
    __shared__ float red[8];

    float qv[4];
    float ss = 0.f;
#pragma unroll
    for (int c = 0; c < 4; c++) {
        qv[c] = g_q[(size_t)b * H_ + tid + 256 * c];
        ss += qv[c] * qv[c];
    }
#pragma unroll
    for (int o = 16; o; o >>= 1) ss += __shfl_xor_sync(0xffffffffu, ss, o);
    if (lane == 0) red[warp] = ss;
    __syncthreads();
    float tot = red[0] + red[1] + red[2] + red[3] + red[4] + red[5] + red[6] + red[7];
    float qinv = rsqrtf(tot);
#pragma unroll
    for (int c = 0; c < 4; c++) q_s[tid + 256 * c] = qv[c] * qinv;
    __syncthreads();

    const int len = lens[b];
    float m = -INFINITY, l = 0.f;
    float acc[4] = {0.f, 0.f, 0.f, 0.f};

    for (int s0 = 0; s0 < len; s0 += 8) {
        int rows = min(8, len - s0);
#pragma unroll
        for (int j = 0; j < 8; j++) {
            if (j < rows) {
                const float4* src = (const float4*)(enc + (((size_t)(s0 + j)) * B_ + b) * H_);
                ((float4*)tile[j])[tid] = src[tid];
            } else {
                ((float4*)tile[j])[tid] = make_float4(0.f, 0.f, 0.f, 0.f);
            }
        }
        __syncthreads();
        if (warp < rows) {
            const float4* trow = (const float4*)tile[warp];
            const float4* qrow = (const float4*)q_s;
            float e = 0.f;
#pragma unroll
            for (int j = 0; j < 8; j++) {
                float4 t = trow[lane + 32 * j];
                float4 q4 = qrow[lane + 32 * j];
                e += t.x * q4.x + t.y * q4.y + t.z * q4.z + t.w * q4.w;
            }
#pragma unroll
            for (int o = 16; o; o >>= 1) e += __shfl_xor_sync(0xffffffffu, e, o);
            if (lane == 0) e_chunk[warp] = e;
        }
        __syncthreads();
        float cm = -INFINITY;
        for (int i = 0; i < rows; i++) cm = fmaxf(cm, e_chunk[i]);
        float m_new = fmaxf(m, cm);
        float scale = (m == -INFINITY) ? 0.f : __expf(m - m_new);
        float p[8];
        float lsum = 0.f;
#pragma unroll
        for (int i = 0; i < 8; i++) {
            p[i] = (i < rows) ? __expf(e_chunk[i] - m_new) : 0.f;
            lsum += p[i];
        }
        l = l * scale + lsum;
#pragma unroll
        for (int c = 0; c < 4; c++) {
            float a = acc[c] * scale;
#pragma unroll
            for (int i = 0; i < 8; i++) a += p[i] * tile[i][tid + 256 * c];
            acc[c] = a;
        }
        m = m_new;
        if (tid < rows) e_all[s0 + tid] = e_chunk[tid];
        __syncthreads();
    }

    float invl = 1.f / l;
#pragma unroll
    for (int c = 0; c < 4; c++) {
        float v = acc[c] * invl;
        g_ctx[(size_t)b * H_ + tid + 256 * c] = v;
        if (out_ctx) out_ctx[(size_t)b * H_ + tid + 256 * c] = v;
    }
    if (out_w) {
        for (int s = tid; s < S_; s += 256) {
            float w = (s < len) ? __expf(e_all[s] - m) * invl : 0.f;
            out_w[(size_t)b * S_ + s] = w;
        }
    }
}

// =====================================================================
// BN stats + final projection
// =====================================================================
__global__ void bn_stats_kernel()
{
    int h = blockIdx.x * blockDim.x + threadIdx.x;
    float s = 0.f, s2 = 0.f;
    for (int b = 0; b < B_; b++) {
        float v = g_y[(size_t)b * H_ + h];
        s += v;
        s2 += v * v;
    }
    float mu = s * (1.f / B_);
    float var = fmaxf(s2 * (1.f / B_) - mu * mu, 0.f);
    g_mu[h] = mu;
    g_rstd[h] = rsqrtf(var + EPSBN);
}

__global__ void out_kernel(const float* __restrict__ gamma,
                           const float* __restrict__ beta,
                           const float* __restrict__ W2,
                           const float* __restrict__ b2,
                           float* __restrict__ out)
{
    int b = blockIdx.x, tid = threadIdx.x;
    int warp = tid >> 5, lane = tid & 31;
    __shared__ float red[3][8];
    float s0 = 0.f, s1 = 0.f, s2 = 0.f;
#pragma unroll
    for (int c = 0; c < 4; c++) {
        int hh = tid + 256 * c;
        float y = g_y[(size_t)b * H_ + hh];
        float yn = (y - g_mu[hh]) * g_rstd[hh] * gamma[hh] + beta[hh];
        s0 += yn * W2[hh];
        s1 += yn * W2[H_ + hh];
        s2 += yn * W2[2 * H_ + hh];
    }
#pragma unroll
    for (int o = 16; o; o >>= 1) {
        s0 += __shfl_xor_sync(0xffffffffu, s0, o);
        s1 += __shfl_xor_sync(0xffffffffu, s1, o);
        s2 += __shfl_xor_sync(0xffffffffu, s2, o);
    }
    if (lane == 0) { red[0][warp] = s0; red[1][warp] = s1; red[2][warp] = s2; }
    __syncthreads();
    if (tid < 3) {
        float t = 0.f;
#pragma unroll
        for (int w = 0; w < 8; w++) t += red[tid][w];
        out[b * 3 + tid] = t + b2[tid];
    }
}

// =====================================================================
// launcher
// =====================================================================
extern "C" void kernel_launch(void* const* d_in, const int* in_sizes, int n_in,
                              void* d_out, int out_size)
{
    const float* palette  = (const float*)d_in[0];
    const float* last_ctx = (const float*)d_in[1];
    const float* last_h   = (const float*)d_in[2];
    const float* enc      = (const float*)d_in[3];
    const int*   lens     = (const int*)d_in[4];
    const float* attn_W = (const float*)d_in[6];
    const float* attn_b = (const float*)d_in[7];
    const float* Wih    = (const float*)d_in[8];
    const float* Whh    = (const float*)d_in[9];
    const float* bih    = (const float*)d_in[10];
    const float* bhh    = (const float*)d_in[11];
    const float* W1     = (const float*)d_in[12];
    const float* b1     = (const float*)d_in[13];
    const float* gamma  = (const float*)d_in[14];
    const float* beta   = (const float*)d_in[15];
    const float* W2     = (const float*)d_in[16];
    const float* b2     = (const float*)d_in[17];

    float* out_main = (float*)d_out;
    float* out_ctx = 0;
    float* out_h = 0;
    float* out_w = 0;
    if (out_size >= B_ * 3 + 2 * B_ * H_ + B_ * S_) {
        out_ctx = out_main + B_ * 3;
        out_h   = out_ctx + B_ * H_;
        out_w   = out_h + B_ * H_;
    }

    float *p_gi, *p_gh, *p_h, *p_q, *p_ctx, *p_y;
    cudaGetSymbolAddress((void**)&p_gi,  g_gi);
    cudaGetSymbolAddress((void**)&p_gh,  g_gh);
    cudaGetSymbolAddress((void**)&p_h,   g_h);
    cudaGetSymbolAddress((void**)&p_q,   g_q);
    cudaGetSymbolAddress((void**)&p_ctx, g_ctx);
    cudaGetSymbolAddress((void**)&p_y,   g_y);

    // 1) gi = [palette | last_context] @ Wih^T + bih  (K = 1027)
    gemm_kernel<<<dim3(3 * H_ / BN, B_ / BM), 256>>>(
        palette, P_, last_ctx, H_, Wih, bih, p_gi, B_, 3 * H_, 0);
    // 2) gh = last_hidden @ Whh^T + bhh
    gemm_kernel<<<dim3(3 * H_ / BN, B_ / BM), 256>>>(
        last_h, H_, (const float*)0, 0, Whh, bhh, p_gh, B_, 3 * H_, 0);
    // 3) gates -> h
    gru_gate_kernel<<<(B_ * H_) / 256, 256>>>(last_h, out_h);
    // 4) q = h @ attn_W^T + attn_b
    gemm_kernel<<<dim3(H_ / BN, B_ / BM), 256>>>(
        p_h, H_, (const float*)0, 0, attn_W, attn_b, p_q, B_, H_, 0);
    // 5) attention -> context + weights
    attn_kernel<<<B_, 256>>>(enc, lens, out_ctx, out_w);
    // 6) y = relu([h | context] @ W1^T + b1)
    gemm_kernel<<<dim3(H_ / BN, B_ / BM), 256>>>(
        p_h, H_, p_ctx, H_, W1, b1, p_y, B_, H_, 1);
    // 7) BN stats
    bn_stats_kernel<<<H_ / 256, 256>>>();
    // 8) final projection
    out_kernel<<<B_, 256>>>(gamma, beta, W2, b2, out_main);
}

// round 2
// speedup vs baseline: 1.8212x; 1.8212x over previous
#include <cuda_runtime.h>
#include <math.h>

#define B_ 256
#define H_ 1024
#define P_ 3
#define S_ 512
#define EPSBN 1e-5f
#define KP 1040            // 1027 padded up to multiple of 16

// ---------------- static device scratch ----------------
__device__ float g_x[B_ * KP];             // packed [palette|ctx|0]
__device__ float g_Wp[3 * H_ * KP];        // packed Wih
__device__ float g_gi[B_ * 3 * H_];
__device__ float g_gh[B_ * 3 * H_];
__device__ float g_hc[B_ * 2 * H_];        // [h | context] rows of 2048
__device__ float g_q[B_ * H_];
__device__ float g_y[B_ * H_];
__device__ float g_mu[H_];
__device__ float g_rstd[H_];
__device__ float g_pm[B_ * 4];
__device__ float g_pl[B_ * 4];
__device__ float g_pacc[B_ * 4 * H_];
__device__ float g_e[B_ * S_];

// =====================================================================
// GEMM core: C[32 x 64 tile] = A[M,K](lda) @ W[N,K](ldw)^T + bias
// 128 threads, 4x4 per thread, double-buffered smem, 1 sync per tile.
// Requires: K % 16 == 0, M % 32 == 0, N % 64 == 0, 16B-aligned rows.
// =====================================================================
#define BM 32
#define BN 64
#define BK 16

__device__ __forceinline__ void gemm_body(
    const float* __restrict__ A, int lda,
    const float* __restrict__ W, int ldw,
    const float* __restrict__ bias,
    float* __restrict__ C, int ldc,
    int K, int relu, int bm0, int bn0)
{
    __shared__ __align__(16) float As[2][BK][BM];
    __shared__ __align__(16) float Bs[2][BK][BN];

    const int tid = threadIdx.x;       // 0..127
    const int tx = tid & 15;           // n-tile 0..15
    const int ty = tid >> 4;           // m-tile 0..7

    const int lr = tid >> 2;           // 0..31 (row for loads)
    const int lk = (tid & 3) << 2;     // 0,4,8,12 (k offset for loads)

    const float* Arow  = A + (size_t)(bm0 + lr) * lda + lk;
    const float* Wrow0 = W + (size_t)(bn0 + lr) * ldw + lk;
    const float* Wrow1 = W + (size_t)(bn0 + 32 + lr) * ldw + lk;

    float4 ra  = *(const float4*)Arow;
    float4 rb0 = *(const float4*)Wrow0;
    float4 rb1 = *(const float4*)Wrow1;

    As[0][lk + 0][lr] = ra.x;  As[0][lk + 1][lr] = ra.y;
    As[0][lk + 2][lr] = ra.z;  As[0][lk + 3][lr] = ra.w;
    Bs[0][lk + 0][lr] = rb0.x; Bs[0][lk + 1][lr] = rb0.y;
    Bs[0][lk + 2][lr] = rb0.z; Bs[0][lk + 3][lr] = rb0.w;
    Bs[0][lk + 0][32 + lr] = rb1.x; Bs[0][lk + 1][32 + lr] = rb1.y;
    Bs[0][lk + 2][32 + lr] = rb1.z; Bs[0][lk + 3][32 + lr] = rb1.w;
    __syncthreads();

    float acc00 = 0.f, acc01 = 0.f, acc02 = 0.f, acc03 = 0.f;
    float acc10 = 0.f, acc11 = 0.f, acc12 = 0.f, acc13 = 0.f;
    float acc20 = 0.f, acc21 = 0.f, acc22 = 0.f, acc23 = 0.f;
    float acc30 = 0.f, acc31 = 0.f, acc32 = 0.f, acc33 = 0.f;

    const int nt = K / BK;
    for (int t = 0; t < nt; t++) {
        const int cur = t & 1;
        if (t + 1 < nt) {
            const int koff = (t + 1) * BK;
            ra  = *(const float4*)(Arow + koff);
            rb0 = *(const float4*)(Wrow0 + koff);
            rb1 = *(const float4*)(Wrow1 + koff);
        }
#pragma unroll
        for (int kk = 0; kk < BK; kk++) {
            float4 a4 = *(const float4*)&As[cur][kk][ty << 2];
            float4 b4 = *(const float4*)&Bs[cur][kk][tx << 2];
            acc00 += a4.x * b4.x; acc01 += a4.x * b4.y;
            acc02 += a4.x * b4.z; acc03 += a4.x * b4.w;
            acc10 += a4.y * b4.x; acc11 += a4.y * b4.y;
            acc12 += a4.y * b4.z; acc13 += a4.y * b4.w;
            acc20 += a4.z * b4.x; acc21 += a4.z * b4.y;
            acc22 += a4.z * b4.z; acc23 += a4.z * b4.w;
            acc30 += a4.w * b4.x; acc31 += a4.w * b4.y;
            acc32 += a4.w * b4.z; acc33 += a4.w * b4.w;
        }
        if (t + 1 < nt) {
            const int nx = cur ^ 1;
            As[nx][lk + 0][lr] = ra.x;  As[nx][lk + 1][lr] = ra.y;
            As[nx][lk + 2][lr] = ra.z;  As[nx][lk + 3][lr] = ra.w;
            Bs[nx][lk + 0][lr] = rb0.x; Bs[nx][lk + 1][lr] = rb0.y;
            Bs[nx][lk + 2][lr] = rb0.z; Bs[nx][lk + 3][lr] = rb0.w;
            Bs[nx][lk + 0][32 + lr] = rb1.x; Bs[nx][lk + 1][32 + lr] = rb1.y;
            Bs[nx][lk + 2][32 + lr] = rb1.z; Bs[nx][lk + 3][32 + lr] = rb1.w;
            __syncthreads();
        }
    }

    const int n0 = bn0 + (tx << 2);
    float bx = bias[n0 + 0], by = bias[n0 + 1], bz = bias[n0 + 2], bw = bias[n0 + 3];
#pragma unroll
    for (int i = 0; i < 4; i++) {
        const int m = bm0 + (ty << 2) + i;
        float4 v;
        v.x = (i == 0 ? acc00 : i == 1 ? acc10 : i == 2 ? acc20 : acc30) + bx;
        v.y = (i == 0 ? acc01 : i == 1 ? acc11 : i == 2 ? acc21 : acc31) + by;
        v.z = (i == 0 ? acc02 : i == 1 ? acc12 : i == 2 ? acc22 : acc32) + bz;
        v.w = (i == 0 ? acc03 : i == 1 ? acc13 : i == 2 ? acc23 : acc33) + bw;
        if (relu) {
            v.x = fmaxf(v.x, 0.f); v.y = fmaxf(v.y, 0.f);
            v.z = fmaxf(v.z, 0.f); v.w = fmaxf(v.w, 0.f);
        }
        *(float4*)&C[(size_t)m * ldc + n0] = v;
    }
}

__global__ void __launch_bounds__(128) gemm_one(
    const float* __restrict__ A, int lda,
    const float* __restrict__ W, int ldw,
    const float* __restrict__ bias,
    float* __restrict__ C, int ldc, int K, int relu)
{
    gemm_body(A, lda, W, ldw, bias, C, ldc, K, relu,
              blockIdx.y * BM, blockIdx.x * BN);
}

// gi (z=0) and gh (z=1) in one launch to fill the chip
__global__ void __launch_bounds__(128) gemm_dual(
    const float* A0, int lda0, const float* W0, int ldw0, const float* b0, float* C0, int K0,
    const float* A1, int lda1, const float* W1p, int ldw1, const float* b1, float* C1, int K1n)
{
    const float* A; int lda; const float* W; int ldw; const float* bias; float* C; int K;
    if (blockIdx.z == 0) { A = A0; lda = lda0; W = W0; ldw = ldw0; bias = b0; C = C0; K = K0; }
    else                 { A = A1; lda = lda1; W = W1p; ldw = ldw1; bias = b1; C = C1; K = K1n; }
    gemm_body(A, lda, W, ldw, bias, C, 3 * H_, K, 0,
              blockIdx.y * BM, blockIdx.x * BN);
}

// =====================================================================
// packing
// =====================================================================
__global__ void pack_x_kernel(const float* __restrict__ palette,
                              const float* __restrict__ ctx)
{
    int idx = blockIdx.x * 256 + threadIdx.x;      // B_*KP threads
    int b = idx / KP, k = idx - b * KP;
    float v = 0.f;
    if (k < P_) v = palette[b * P_ + k];
    else if (k < P_ + H_) v = ctx[b * H_ + (k - P_)];
    g_x[idx] = v;
}

__global__ void pack_w_kernel(const float* __restrict__ Wih)
{
    int idx = blockIdx.x * 256 + threadIdx.x;      // 3H*KP threads
    int n = idx / KP, k = idx - n * KP;
    g_Wp[idx] = (k < H_ + P_) ? Wih[(size_t)n * (H_ + P_) + k] : 0.f;
}

// =====================================================================
// GRU gates: h = (1-z)*n + z*h0  -> g_hc[:, :H] and out_h
// =====================================================================
__global__ void gru_gate_kernel(const float* __restrict__ h0,
                                float* __restrict__ out_h)
{
    int idx = blockIdx.x * 256 + threadIdx.x;
    int b = idx >> 10;
    int j = idx & (H_ - 1);
    size_t base = (size_t)b * (3 * H_);
    float gir = g_gi[base + j];
    float giz = g_gi[base + H_ + j];
    float gin = g_gi[base + 2 * H_ + j];
    float ghr = g_gh[base + j];
    float ghz = g_gh[base + H_ + j];
    float ghn = g_gh[base + 2 * H_ + j];
    float r = 1.f / (1.f + __expf(-(gir + ghr)));
    float z = 1.f / (1.f + __expf(-(giz + ghz)));
    float n = tanhf(gin + r * ghn);
    float h = (1.f - z) * n + z * h0[idx];
    g_hc[(size_t)b * (2 * H_) + j] = h;
    if (out_h) out_h[idx] = h;
}

// =====================================================================
// Attention, split along seq into 4 partitions per batch row.
// grid (B, 4), 256 threads. Online softmax partials + energies to gmem.
// =====================================================================
__global__ void attn_part_kernel(const float* __restrict__ enc,
                                 const int* __restrict__ lens)
{
    const int b = blockIdx.x;
    const int p = blockIdx.y;
    const int tid = threadIdx.x;
    const int warp = tid >> 5, lane = tid & 31;

    __shared__ __align__(16) float q_s[H_];
    __shared__ __align__(16) float tile[8][H_];
    __shared__ float e_chunk[8];
    __shared__ float red[8];

    // load + L2-normalize q (redundant per partition, cheap)
    float qv[4];
    float ss = 0.f;
#pragma unroll
    for (int c = 0; c < 4; c++) {
        qv[c] = g_q[(size_t)b * H_ + tid + 256 * c];
        ss += qv[c] * qv[c];
    }
#pragma unroll
    for (int o = 16; o; o >>= 1) ss += __shfl_xor_sync(0xffffffffu, ss, o);
    if (lane == 0) red[warp] = ss;
    __syncthreads();
    float tot = red[0] + red[1] + red[2] + red[3] + red[4] + red[5] + red[6] + red[7];
    float qinv = rsqrtf(tot);
#pragma unroll
    for (int c = 0; c < 4; c++) q_s[tid + 256 * c] = qv[c] * qinv;
    __syncthreads();

    const int len = lens[b];
    const int sb = p * (S_ / 4);
    const int se = min(len, sb + (S_ / 4));

    float m = -INFINITY, l = 0.f;
    float acc[4] = {0.f, 0.f, 0.f, 0.f};

    for (int s0 = sb; s0 < se; s0 += 8) {
        int rows = min(8, se - s0);
#pragma unroll
        for (int j = 0; j < 8; j++) {
            if (j < rows) {
                const float4* src = (const float4*)(enc + (((size_t)(s0 + j)) * B_ + b) * H_);
                ((float4*)tile[j])[tid] = src[tid];
            } else {
                ((float4*)tile[j])[tid] = make_float4(0.f, 0.f, 0.f, 0.f);
            }
        }
        __syncthreads();
        if (warp < rows) {
            const float4* trow = (const float4*)tile[warp];
            const float4* qrow = (const float4*)q_s;
            float e = 0.f;
#pragma unroll
            for (int j = 0; j < 8; j++) {
                float4 t = trow[lane + 32 * j];
                float4 q4 = qrow[lane + 32 * j];
                e += t.x * q4.x + t.y * q4.y + t.z * q4.z + t.w * q4.w;
            }
#pragma unroll
            for (int o = 16; o; o >>= 1) e += __shfl_xor_sync(0xffffffffu, e, o);
            if (lane == 0) e_chunk[warp] = e;
        }
        __syncthreads();
        float cm = -INFINITY;
        for (int i = 0; i < rows; i++) cm = fmaxf(cm, e_chunk[i]);
        float m_new = fmaxf(m, cm);
        float scale = (m == -INFINITY) ? 0.f : __expf(m - m_new);
        float pr[8];
        float lsum = 0.f;
#pragma unroll
        for (int i = 0; i < 8; i++) {
            pr[i] = (i < rows) ? __expf(e_chunk[i] - m_new) : 0.f;
            lsum += pr[i];
        }
        l = l * scale + lsum;
#pragma unroll
        for (int c = 0; c < 4; c++) {
            float a = acc[c] * scale;
#pragma unroll
            for (int i = 0; i < 8; i++) a += pr[i] * tile[i][tid + 256 * c];
            acc[c] = a;
        }
        m = m_new;
        if (tid < rows) g_e[(size_t)b * S_ + s0 + tid] = e_chunk[tid];
        __syncthreads();
    }

    if (tid == 0) { g_pm[b * 4 + p] = m; g_pl[b * 4 + p] = l; }
#pragma unroll
    for (int c = 0; c < 4; c++)
        g_pacc[((size_t)(b * 4 + p)) * H_ + tid + 256 * c] = acc[c];
}

// combine partials -> context (into g_hc[:, H:]) + attn weights
__global__ void attn_comb_kernel(const int* __restrict__ lens,
                                 float* __restrict__ out_ctx,
                                 float* __restrict__ out_w)
{
    const int b = blockIdx.x;
    const int tid = threadIdx.x;

    float mp[4], lp[4];
#pragma unroll
    for (int p = 0; p < 4; p++) { mp[p] = g_pm[b * 4 + p]; lp[p] = g_pl[b * 4 + p]; }
    float m = fmaxf(fmaxf(mp[0], mp[1]), fmaxf(mp[2], mp[3]));
    float sc[4];
    float l = 0.f;
#pragma unroll
    for (int p = 0; p < 4; p++) {
        sc[p] = (lp[p] > 0.f) ? __expf(mp[p] - m) : 0.f;
        l += lp[p] * sc[p];
    }
    float invl = 1.f / l;

#pragma unroll
    for (int c = 0; c < 4; c++) {
        int h = tid + 256 * c;
        float v = 0.f;
#pragma unroll
        for (int p = 0; p < 4; p++)
            v += g_pacc[((size_t)(b * 4 + p)) * H_ + h] * sc[p];
        v *= invl;
        g_hc[(size_t)b * (2 * H_) + H_ + h] = v;
        if (out_ctx) out_ctx[(size_t)b * H_ + h] = v;
    }

    if (out_w) {
        int len = lens[b];
        for (int s = tid; s < S_; s += 256) {
            float w = (s < len) ? __expf(g_e[(size_t)b * S_ + s] - m) * invl : 0.f;
            out_w[(size_t)b * S_ + s] = w;
        }
    }
}

// =====================================================================
// BN stats + final projection
// =====================================================================
__global__ void bn_stats_kernel()
{
    int h = blockIdx.x * 256 + threadIdx.x;
    float s = 0.f, s2 = 0.f;
    for (int b = 0; b < B_; b++) {
        float v = g_y[(size_t)b * H_ + h];
        s += v;
        s2 += v * v;
    }
    float mu = s * (1.f / B_);
    float var = fmaxf(s2 * (1.f / B_) - mu * mu, 0.f);
    g_mu[h] = mu;
    g_rstd[h] = rsqrtf(var + EPSBN);
}

__global__ void out_kernel(const float* __restrict__ gamma,
                           const float* __restrict__ beta,
                           const float* __restrict__ W2,
                           const float* __restrict__ b2,
                           float* __restrict__ out)
{
    int b = blockIdx.x, tid = threadIdx.x;
    int warp = tid >> 5, lane = tid & 31;
    __shared__ float red[3][8];
    float s0 = 0.f, s1 = 0.f, s2 = 0.f;
#pragma unroll
    for (int c = 0; c < 4; c++) {
        int hh = tid + 256 * c;
        float y = g_y[(size_t)b * H_ + hh];
        float yn = (y - g_mu[hh]) * g_rstd[hh] * gamma[hh] + beta[hh];
        s0 += yn * W2[hh];
        s1 += yn * W2[H_ + hh];
        s2 += yn * W2[2 * H_ + hh];
    }
#pragma unroll
    for (int o = 16; o; o >>= 1) {
        s0 += __shfl_xor_sync(0xffffffffu, s0, o);
        s1 += __shfl_xor_sync(0xffffffffu, s1, o);
        s2 += __shfl_xor_sync(0xffffffffu, s2, o);
    }
    if (lane == 0) { red[0][warp] = s0; red[1][warp] = s1; red[2][warp] = s2; }
    __syncthreads();
    if (tid < 3) {
        float t = 0.f;
#pragma unroll
        for (int w = 0; w < 8; w++) t += red[tid][w];
        out[b * 3 + tid] = t + b2[tid];
    }
}

// =====================================================================
// launcher
// =====================================================================
extern "C" void kernel_launch(void* const* d_in, const int* in_sizes, int n_in,
                              void* d_out, int out_size)
{
    const float* palette  = (const float*)d_in[0];
    const float* last_ctx = (const float*)d_in[1];
    const float* last_h   = (const float*)d_in[2];
    const float* enc      = (const float*)d_in[3];
    const int*   lens     = (const int*)d_in[4];
    const float* attn_W = (const float*)d_in[6];
    const float* attn_b = (const float*)d_in[7];
    const float* Wih    = (const float*)d_in[8];
    const float* Whh    = (const float*)d_in[9];
    const float* bih    = (const float*)d_in[10];
    const float* bhh    = (const float*)d_in[11];
    const float* W1     = (const float*)d_in[12];
    const float* b1     = (const float*)d_in[13];
    const float* gamma  = (const float*)d_in[14];
    const float* beta   = (const float*)d_in[15];
    const float* W2     = (const float*)d_in[16];
    const float* b2     = (const float*)d_in[17];

    float* out_main = (float*)d_out;
    float* out_ctx = 0;
    float* out_h = 0;
    float* out_w = 0;
    if (out_size >= B_ * 3 + 2 * B_ * H_ + B_ * S_) {
        out_ctx = out_main + B_ * 3;
        out_h   = out_ctx + B_ * H_;
        out_w   = out_h + B_ * H_;
    }

    float *p_x, *p_Wp, *p_gi, *p_gh, *p_hc, *p_q, *p_y;
    cudaGetSymbolAddress((void**)&p_x,  g_x);
    cudaGetSymbolAddress((void**)&p_Wp, g_Wp);
    cudaGetSymbolAddress((void**)&p_gi, g_gi);
    cudaGetSymbolAddress((void**)&p_gh, g_gh);
    cudaGetSymbolAddress((void**)&p_hc, g_hc);
    cudaGetSymbolAddress((void**)&p_q,  g_q);
    cudaGetSymbolAddress((void**)&p_y,  g_y);

    // 0) pack x=[palette|ctx] to K=1040, pack Wih likewise
    pack_x_kernel<<<(B_ * KP) / 256, 256>>>(palette, last_ctx);
    pack_w_kernel<<<(3 * H_ * KP) / 256, 256>>>(Wih);

    // 1) fused gi/gh GEMMs: grid (48, 8, 2) = 768 blocks
    gemm_dual<<<dim3(3 * H_ / BN, B_ / BM, 2), 128>>>(
        p_x, KP, p_Wp, KP, bih, p_gi, KP,
        last_h, H_, Whh, H_, bhh, p_gh, H_);

    // 2) gates -> h (into g_hc[:, :H] and out_h)
    gru_gate_kernel<<<(B_ * H_) / 256, 256>>>(last_h, out_h);

    // 3) q = h @ attn_W^T + attn_b
    gemm_one<<<dim3(H_ / BN, B_ / BM), 128>>>(
        p_hc, 2 * H_, attn_W, H_, attn_b, p_q, H_, H_, 0);

    // 4) attention: 4 seq partitions per batch row, then combine
    attn_part_kernel<<<dim3(B_, 4), 256>>>(enc, lens);
    attn_comb_kernel<<<B_, 256>>>(lens, out_ctx, out_w);

    // 5) y = relu([h|ctx] @ W1^T + b1)
    gemm_one<<<dim3(H_ / BN, B_ / BM), 128>>>(
        p_hc, 2 * H_, W1, 2 * H_, b1, p_y, H_, 2 * H_, 1);

    // 6) BN stats + final projection
    bn_stats_kernel<<<H_ / 256, 256>>>();
    out_kernel<<<B_, 256>>>(gamma, beta, W2, b2, out_main);
}